// round 12
// baseline (speedup 1.0000x reference)
#include <cuda_runtime.h>
#include <cuda_bf16.h>

#define NB 64
#define NS 500
#define NH 512
#define NV 3
#define NT 500
#define GRID 128
#define NTHR 512

// ---- smem layout (floats) ----
#define W1T_OFF 0               // [1536][16]
#define W2T_OFF 24576           // [1024][16]
#define WORK_OFF 40960          // union: attn {sc,wts,pacc,red,red2,ctl} | lstm {xs[4],pt[3]}
#define SC_OFF   40960          // [256]
#define WTS_OFF  41216          // [256]
#define PACC_OFF 41472          // [256][4]
#define RED_OFF  42496          // [16]
#define RED2_OFF 42512          // [16]
#define CTL_OFF  42528          // [4]
#define XS_OFF   40960          // 4 x [32][64] = 8192
#define PT_OFF   49152          // 3 x [128][8] = 3072
#define H2_OFF  56320           // 512
#define S0_OFF  56832           // 64
#define S1_OFF  56896           // 64
#define LG_OFF  56960           // 4
#define SMEM_FLOATS 56964
#define SMEM_BYTES (SMEM_FLOATS * 4)

// ---------------- device state ----------------
__device__ __align__(16) __nv_bfloat16 g_ctxb[(size_t)NB * NS * 1024];  // 65.5 MB full ctx (bf16)
__device__ __align__(16) __nv_bfloat16 g_ctxs[(size_t)NB * NS * 512];   // 32.8 MB folded ctx
__device__ __align__(16) float g_apart[2][NB][1024];
__device__ float g_m[NB][2];
__device__ float g_l[NB][2];
__device__ __align__(16) float g_h1[2][NB][NH];
__device__ __align__(16) float g_c1[NB][NH];
__device__ __align__(16) float g_h2[2][NB][NH];
__device__ __align__(16) float g_c2[NB][NH];
__device__ __align__(16) float g_E[NV][4][NH];
__device__ __align__(16) float g_B2[4][NH];
__device__ int g_idx[NB];

__device__ unsigned g_count = 0;
__device__ volatile unsigned g_epoch = 0;

__device__ __forceinline__ void gbar() {
    __syncthreads();                      // CTA writes happen-before tid0's fence
    if (threadIdx.x == 0) {
        __threadfence();
        unsigned e = g_epoch;
        if (atomicAdd(&g_count, 1) == GRID - 1) {
            g_count = 0;
            __threadfence();
            g_epoch = e + 1;
        } else {
            int it = 0;
            while (g_epoch == e) { if ((++it & 63) == 0) __nanosleep(64); }
        }
        __threadfence();
    }
    __syncthreads();
}

__device__ __forceinline__ float2 ffma2(float2 a, float2 b, float2 c) {
    float2 d;
    asm("fma.rn.f32x2 %0, %1, %2, %3;"
        : "=l"(*reinterpret_cast<unsigned long long*>(&d))
        : "l"(*reinterpret_cast<unsigned long long*>(&a)),
          "l"(*reinterpret_cast<unsigned long long*>(&b)),
          "l"(*reinterpret_cast<unsigned long long*>(&c)));
    return d;
}

__device__ __forceinline__ float sigm(float x) { return 1.f / (1.f + expf(-x)); }

// bf16x2 (packed in u32) -> two fp32
__device__ __forceinline__ float2 bf2f(unsigned u) {
    float2 f;
    f.x = __uint_as_float(u << 16);
    f.y = __uint_as_float(u & 0xffff0000u);
    return f;
}

// dot of one folded row (2 x uint4 = 16 bf16-pairs... 512 dims via 2 chunks) vs h2
__device__ __forceinline__ float row_dot512(uint4 u0, uint4 u1,
                                            float4 ha, float4 hb, float4 hc, float4 hd) {
    float s = 0.f; float2 p;
    p = bf2f(u0.x); s += p.x * ha.x + p.y * ha.y;
    p = bf2f(u0.y); s += p.x * ha.z + p.y * ha.w;
    p = bf2f(u0.z); s += p.x * hb.x + p.y * hb.y;
    p = bf2f(u0.w); s += p.x * hb.z + p.y * hb.w;
    p = bf2f(u1.x); s += p.x * hc.x + p.y * hc.y;
    p = bf2f(u1.y); s += p.x * hc.z + p.y * hc.w;
    p = bf2f(u1.z); s += p.x * hd.x + p.y * hd.y;
    p = bf2f(u1.w); s += p.x * hd.z + p.y * hd.w;
    return s;
}

// ---------------- attention: direct-L2, folded scores ----------------
__device__ void attn_phase(const float* __restrict__ Wl,
                           const float* __restrict__ blv, float* __restrict__ out,
                           int t, int blk, float* smem) {
    int p = t & 1;
    int b = blk >> 1, h = blk & 1;
    int tid = threadIdx.x;
    int warp = tid >> 5, lane = tid & 31;
    float* h2s  = smem + H2_OFF;
    float* sc   = smem + SC_OFF;
    float* wts  = smem + WTS_OFF;
    float* pacc = smem + PACC_OFF;
    float* red  = smem + RED_OFF;
    float* red2 = smem + RED2_OFF;
    float* ctl  = smem + CTL_OFF;
    float* lg   = smem + LG_OFF;

    const float* h2g = g_h2[p][b];
    h2s[tid] = h2g[tid];

    // ---- logits / argmax / log_softmax for step t-1 ----
    if (h == 0 && t > 0) {
        if (warp < 3) {
            const float* wr = Wl + warp * 512;
            float s = 0.f;
            for (int i = lane; i < 512; i += 32) s += wr[i] * h2g[i];
            for (int o = 16; o; o >>= 1) s += __shfl_xor_sync(0xffffffffu, s, o);
            if (!lane) lg[warp] = s + blv[warp];
        }
        __syncthreads();
        if (tid == 0) {
            float l0 = lg[0], l1 = lg[1], l2 = lg[2];
            int bi = 0; float bv = l0;
            if (l1 > bv) { bv = l1; bi = 1; }
            if (l2 > bv) { bv = l2; bi = 2; }
            g_idx[b] = bi;
            float lse = bv + logf(expf(l0 - bv) + expf(l1 - bv) + expf(l2 - bv));
            float* o = out + ((size_t)b * NT + (t - 1)) * 3;
            o[0] = l0 - lse; o[1] = l1 - lse; o[2] = l2 - lse;
        }
    }
    if (t >= NT) return;
    __syncthreads();   // h2s ready (also orders lg block)

    const __nv_bfloat16* gbase = g_ctxb + ((size_t)(b * NS + h * 250)) * 1024;
    const __nv_bfloat16* sbase = g_ctxs + ((size_t)(b * NS + h * 250)) * 512;

    // ---- pass A: scores on folded rows (512 dims). warp w: rows w, w+16, ... ----
    {
        float4 ha = ((const float4*)h2s)[2 * lane];
        float4 hb = ((const float4*)h2s)[2 * lane + 1];
        float4 hc = ((const float4*)h2s)[64 + 2 * lane];
        float4 hd = ((const float4*)h2s)[64 + 2 * lane + 1];
        const uint4 z4 = make_uint4(0, 0, 0, 0);
#pragma unroll
        for (int i = 0; i < 16; i += 2) {
            int r0 = warp + 16 * i;
            int r1 = r0 + 16;
            bool v0 = r0 < 250, v1 = r1 < 250;
            const uint4* rp0 = (const uint4*)(sbase + (size_t)r0 * 512);
            const uint4* rp1 = (const uint4*)(sbase + (size_t)r1 * 512);
            uint4 A0 = z4, A1 = z4, B0 = z4, B1 = z4;
            if (v0) { A0 = rp0[lane]; A1 = rp0[32 + lane]; }
            if (v1) { B0 = rp1[lane]; B1 = rp1[32 + lane]; }
            float s0 = row_dot512(A0, A1, ha, hb, hc, hd);
            float s1 = row_dot512(B0, B1, ha, hb, hc, hd);
            for (int o = 16; o; o >>= 1) {
                s0 += __shfl_xor_sync(0xffffffffu, s0, o);
                s1 += __shfl_xor_sync(0xffffffffu, s1, o);
            }
            if (!lane) {
                if (v0) sc[r0] = s0;
                if (v1) sc[r1] = s1;
            }
        }
    }
    __syncthreads();

    // ---- pass B: softmax stats ----
    {
        float v = (tid < 250) ? sc[tid] : -1e30f;
        float mv = v;
        for (int o = 16; o; o >>= 1) mv = fmaxf(mv, __shfl_xor_sync(0xffffffffu, mv, o));
        if (!lane) red[warp] = mv;
    }
    __syncthreads();
    if (warp == 0) {
        float mv = (lane < 16) ? red[lane] : -1e30f;
        for (int o = 8; o; o >>= 1) mv = fmaxf(mv, __shfl_xor_sync(0xffffffffu, mv, o));
        if (!lane) ctl[0] = mv;
    }
    __syncthreads();
    {
        float m = ctl[0];
        float w = (tid < 250) ? __expf(sc[tid] - m) : 0.f;
        if (tid < 250) wts[tid] = w;
        for (int o = 16; o; o >>= 1) w += __shfl_xor_sync(0xffffffffu, w, o);
        if (!lane) red2[warp] = w;
    }
    __syncthreads();   // wts + red2 visible

    // ---- pass C: accumulate. group g rows [125g,125g+125), thread owns 4 dims ----
    {
        int g = tid >> 8, tl = tid & 255;
        const __nv_bfloat16* base2 = gbase + 4 * tl + (size_t)(g * 125) * 1024;
        float4 acc0 = make_float4(0.f, 0.f, 0.f, 0.f);
        float4 acc1 = make_float4(0.f, 0.f, 0.f, 0.f);
        const float* wp2 = wts + g * 125;
#pragma unroll 6
        for (int r = 0; r < 124; r += 2) {
            float w0 = wp2[r], w1 = wp2[r + 1];
            uint2 q0 = *(const uint2*)(base2 + (size_t)r * 1024);
            uint2 q1 = *(const uint2*)(base2 + (size_t)(r + 1) * 1024);
            float2 a0 = bf2f(q0.x), a1 = bf2f(q0.y);
            float2 b0 = bf2f(q1.x), b1 = bf2f(q1.y);
            acc0.x += w0 * a0.x; acc0.y += w0 * a0.y;
            acc0.z += w0 * a1.x; acc0.w += w0 * a1.y;
            acc1.x += w1 * b0.x; acc1.y += w1 * b0.y;
            acc1.z += w1 * b1.x; acc1.w += w1 * b1.y;
        }
        {   // r = 124
            float w0 = wp2[124];
            uint2 q0 = *(const uint2*)(base2 + (size_t)124 * 1024);
            float2 a0 = bf2f(q0.x), a1 = bf2f(q0.y);
            acc0.x += w0 * a0.x; acc0.y += w0 * a0.y;
            acc0.z += w0 * a1.x; acc0.w += w0 * a1.y;
        }
        float4 acc = make_float4(acc0.x + acc1.x, acc0.y + acc1.y,
                                 acc0.z + acc1.z, acc0.w + acc1.w);
        if (g == 1) ((float4*)pacc)[tl] = acc;
        __syncthreads();
        if (g == 0) {
            float4 o = ((float4*)pacc)[tl];
            acc.x += o.x; acc.y += o.y; acc.z += o.z; acc.w += o.w;
            ((float4*)g_apart[h][b])[tl] = acc;
            if (tl == 0) {
                g_m[b][h] = ctl[0];
                float l = 0.f;
#pragma unroll
                for (int i = 0; i < 16; i++) l += red2[i];
                g_l[b][h] = l;
            }
        }
    }
}

// ---------------- LSTM 1: 4-way split-K, 2 j-columns per thread ----------------
__device__ void lstm1_phase(int t, int cb, float* smem) {
    int p = t & 1, q = p ^ 1;
    int tid = threadIdx.x;
    int quar = tid >> 7, tl = tid & 127;
    int b = tl & 63, jj = tl >> 6;
    float* s0s = smem + S0_OFF;
    float* s1s = smem + S1_OFF;
    float* xsq = smem + XS_OFF + quar * 2048;
    const float4* wp = (const float4*)(smem + W1T_OFF);

    if (tid < 64) {
        float m0 = g_m[tid][0], m1 = g_m[tid][1];
        float M = fmaxf(m0, m1);
        float e0 = __expf(m0 - M), e1 = __expf(m1 - M);
        float L = g_l[tid][0] * e0 + g_l[tid][1] * e1;
        s0s[tid] = e0 / L; s1s[tid] = e1 / L;
    }

    int jc0 = cb * 4 + jj, jc1 = jc0 + 2;
    float2 A0g01, A0g23, A1g01, A1g23;
    if (quar == 0) {
        int vv = g_idx[b];
        A0g01 = make_float2(g_E[vv][0][jc0], g_E[vv][1][jc0]);
        A0g23 = make_float2(g_E[vv][2][jc0], g_E[vv][3][jc0]);
        A1g01 = make_float2(g_E[vv][0][jc1], g_E[vv][1][jc1]);
        A1g23 = make_float2(g_E[vv][2][jc1], g_E[vv][3][jc1]);
    } else {
        A0g01 = make_float2(0.f, 0.f); A0g23 = make_float2(0.f, 0.f);
        A1g01 = make_float2(0.f, 0.f); A1g23 = make_float2(0.f, 0.f);
    }

    int bq = tl >> 1;
    int kh = (tl & 1) * 16;
    int kbase = quar * 384;

    for (int kt = 0; kt < 12; kt++) {
        int kb = kbase + kt * 32;
        __syncthreads();
        int k0 = kb + kh;
        if (k0 < 1024) {
            float s0v = s0s[bq], s1v = s1s[bq];
#pragma unroll
            for (int m4 = 0; m4 < 4; m4++) {
                float4 xa = *(const float4*)&g_apart[0][bq][k0 + m4 * 4];
                float4 xb = *(const float4*)&g_apart[1][bq][k0 + m4 * 4];
                xsq[(kh + m4 * 4 + 0) * 64 + bq] = s0v * xa.x + s1v * xb.x;
                xsq[(kh + m4 * 4 + 1) * 64 + bq] = s0v * xa.y + s1v * xb.y;
                xsq[(kh + m4 * 4 + 2) * 64 + bq] = s0v * xa.z + s1v * xb.z;
                xsq[(kh + m4 * 4 + 3) * 64 + bq] = s0v * xa.w + s1v * xb.w;
            }
        } else {
#pragma unroll
            for (int m4 = 0; m4 < 4; m4++) {
                float4 xa = *(const float4*)&g_h1[p][bq][k0 - 1024 + m4 * 4];
                xsq[(kh + m4 * 4 + 0) * 64 + bq] = xa.x;
                xsq[(kh + m4 * 4 + 1) * 64 + bq] = xa.y;
                xsq[(kh + m4 * 4 + 2) * 64 + bq] = xa.z;
                xsq[(kh + m4 * 4 + 3) * 64 + bq] = xa.w;
            }
        }
        __syncthreads();
#pragma unroll
        for (int k = 0; k < 32; k++) {
            float x = xsq[k * 64 + b];
            float4 w0 = wp[(kb + k) * 4 + jj];
            float4 w1 = wp[(kb + k) * 4 + jj + 2];
            float2 xx = make_float2(x, x);
            A0g01 = ffma2(make_float2(w0.x, w0.y), xx, A0g01);
            A0g23 = ffma2(make_float2(w0.z, w0.w), xx, A0g23);
            A1g01 = ffma2(make_float2(w1.x, w1.y), xx, A1g01);
            A1g23 = ffma2(make_float2(w1.z, w1.w), xx, A1g23);
        }
    }
    if (quar) {
        float4* dst = (float4*)(smem + PT_OFF + (quar - 1) * 1024);
        dst[tl * 2]     = make_float4(A0g01.x, A0g01.y, A0g23.x, A0g23.y);
        dst[tl * 2 + 1] = make_float4(A1g01.x, A1g01.y, A1g23.x, A1g23.y);
    }
    __syncthreads();
    if (quar == 0) {
        const float4* p1 = (const float4*)(smem + PT_OFF);
        const float4* p2 = (const float4*)(smem + PT_OFF + 1024);
        const float4* p3 = (const float4*)(smem + PT_OFF + 2048);
        float4 u = p1[tl * 2], v = p2[tl * 2], w = p3[tl * 2];
        float4 a = make_float4(A0g01.x + u.x + v.x + w.x, A0g01.y + u.y + v.y + w.y,
                               A0g23.x + u.z + v.z + w.z, A0g23.y + u.w + v.w + w.w);
        float si = sigm(a.x), sf = sigm(a.y), so = sigm(a.w);
        float tg = tanhf(a.z);
        float cn = sf * g_c1[b][jc0] + si * tg;
        g_c1[b][jc0] = cn;
        g_h1[q][b][jc0] = so * tanhf(cn);
        u = p1[tl * 2 + 1]; v = p2[tl * 2 + 1]; w = p3[tl * 2 + 1];
        a = make_float4(A1g01.x + u.x + v.x + w.x, A1g01.y + u.y + v.y + w.y,
                        A1g23.x + u.z + v.z + w.z, A1g23.y + u.w + v.w + w.w);
        si = sigm(a.x); sf = sigm(a.y); so = sigm(a.w);
        tg = tanhf(a.z);
        cn = sf * g_c1[b][jc1] + si * tg;
        g_c1[b][jc1] = cn;
        g_h1[q][b][jc1] = so * tanhf(cn);
    }
}

// ---------------- LSTM 2: 4-way split-K, 2 j-columns per thread ----------------
__device__ void lstm2_phase(int t, int cb, float* smem) {
    int p = t & 1, q = p ^ 1;
    int tid = threadIdx.x;
    int quar = tid >> 7, tl = tid & 127;
    int b = tl & 63, jj = tl >> 6;
    float* xsq = smem + XS_OFF + quar * 2048;
    const float4* wp = (const float4*)(smem + W2T_OFF);

    int jc0 = cb * 4 + jj, jc1 = jc0 + 2;
    float2 A0g01, A0g23, A1g01, A1g23;
    if (quar == 0) {
        A0g01 = make_float2(g_B2[0][jc0], g_B2[1][jc0]);
        A0g23 = make_float2(g_B2[2][jc0], g_B2[3][jc0]);
        A1g01 = make_float2(g_B2[0][jc1], g_B2[1][jc1]);
        A1g23 = make_float2(g_B2[2][jc1], g_B2[3][jc1]);
    } else {
        A0g01 = make_float2(0.f, 0.f); A0g23 = make_float2(0.f, 0.f);
        A1g01 = make_float2(0.f, 0.f); A1g23 = make_float2(0.f, 0.f);
    }

    int bq = tl >> 1;
    int kh = (tl & 1) * 16;
    int kbase = quar * 256;

    for (int kt = 0; kt < 8; kt++) {
        int kb = kbase + kt * 32;
        __syncthreads();
        int k0 = kb + kh;
        const float* src = (k0 < 512) ? &g_h1[q][bq][k0] : &g_h2[p][bq][k0 - 512];
#pragma unroll
        for (int m4 = 0; m4 < 4; m4++) {
            float4 xa = *(const float4*)(src + m4 * 4);
            xsq[(kh + m4 * 4 + 0) * 64 + bq] = xa.x;
            xsq[(kh + m4 * 4 + 1) * 64 + bq] = xa.y;
            xsq[(kh + m4 * 4 + 2) * 64 + bq] = xa.z;
            xsq[(kh + m4 * 4 + 3) * 64 + bq] = xa.w;
        }
        __syncthreads();
#pragma unroll
        for (int k = 0; k < 32; k++) {
            float x = xsq[k * 64 + b];
            float4 w0 = wp[(kb + k) * 4 + jj];
            float4 w1 = wp[(kb + k) * 4 + jj + 2];
            float2 xx = make_float2(x, x);
            A0g01 = ffma2(make_float2(w0.x, w0.y), xx, A0g01);
            A0g23 = ffma2(make_float2(w0.z, w0.w), xx, A0g23);
            A1g01 = ffma2(make_float2(w1.x, w1.y), xx, A1g01);
            A1g23 = ffma2(make_float2(w1.z, w1.w), xx, A1g23);
        }
    }
    if (quar) {
        float4* dst = (float4*)(smem + PT_OFF + (quar - 1) * 1024);
        dst[tl * 2]     = make_float4(A0g01.x, A0g01.y, A0g23.x, A0g23.y);
        dst[tl * 2 + 1] = make_float4(A1g01.x, A1g01.y, A1g23.x, A1g23.y);
    }
    __syncthreads();
    if (quar == 0) {
        const float4* p1 = (const float4*)(smem + PT_OFF);
        const float4* p2 = (const float4*)(smem + PT_OFF + 1024);
        const float4* p3 = (const float4*)(smem + PT_OFF + 2048);
        float4 u = p1[tl * 2], v = p2[tl * 2], w = p3[tl * 2];
        float4 a = make_float4(A0g01.x + u.x + v.x + w.x, A0g01.y + u.y + v.y + w.y,
                               A0g23.x + u.z + v.z + w.z, A0g23.y + u.w + v.w + w.w);
        float si = sigm(a.x), sf = sigm(a.y), so = sigm(a.w);
        float tg = tanhf(a.z);
        float cn = sf * g_c2[b][jc0] + si * tg;
        g_c2[b][jc0] = cn;
        g_h2[q][b][jc0] = so * tanhf(cn);
        u = p1[tl * 2 + 1]; v = p2[tl * 2 + 1]; w = p3[tl * 2 + 1];
        a = make_float4(A1g01.x + u.x + v.x + w.x, A1g01.y + u.y + v.y + w.y,
                        A1g23.x + u.z + v.z + w.z, A1g23.y + u.w + v.w + w.w);
        si = sigm(a.x); sf = sigm(a.y); so = sigm(a.w);
        tg = tanhf(a.z);
        cn = sf * g_c2[b][jc1] + si * tg;
        g_c2[b][jc1] = cn;
        g_h2[q][b][jc1] = so * tanhf(cn);
    }
}

// ---------------- persistent kernel ----------------
__global__ void __launch_bounds__(NTHR, 1)
k_persist(const float* __restrict__ ctx, const int* __restrict__ tgt,
          const float* __restrict__ h1_0, const float* __restrict__ c1_0,
          const float* __restrict__ h2_0, const float* __restrict__ c2_0,
          const float* __restrict__ emb,
          const float* __restrict__ W_ih0, const float* __restrict__ W_hh0,
          const float* __restrict__ b_ih0, const float* __restrict__ b_hh0,
          const float* __restrict__ W_ih1, const float* __restrict__ W_hh1,
          const float* __restrict__ b_ih1, const float* __restrict__ b_hh1,
          const float* __restrict__ Wl, const float* __restrict__ blv,
          float* __restrict__ out, int out_size) {
    extern __shared__ __align__(16) float smem[];
    int blk = blockIdx.x;
    int tid = threadIdx.x;
    int warp = tid >> 5, lane = tid & 31;

    // ---- setup ----
    {
        int gi = blk * NTHR + tid;
        if (gi < NB * NH) {
            ((float*)g_h1[0])[gi] = h1_0[gi];
            ((float*)g_c1)[gi]    = c1_0[gi];
            ((float*)g_h2[0])[gi] = h2_0[gi];
            ((float*)g_c2)[gi]    = c2_0[gi];
        }
        if (gi < 4 * NH) ((float*)g_B2)[gi] = b_ih1[gi] + b_hh1[gi];
        if (blk == 0 && tid < NB) g_idx[tid] = tgt[tid * NT];
        // fp32 ctx -> bf16 full copy
        for (int i = gi; i < NB * NS * 512; i += GRID * NTHR) {
            float2 v = ((const float2*)ctx)[i];
            ((__nv_bfloat162*)g_ctxb)[i] = __floats2bfloat162_rn(v.x, v.y);
        }
        // folded score table: g_ctxs[bs][d] = ctx[bs][d] + ctx[bs][d+512]  (fp32 fold, one bf16 round)
        for (int i = gi; i < NB * NS * 256; i += GRID * NTHR) {
            int bs = i >> 8, d2 = (i & 255) * 2;
            const float* base = ctx + (size_t)bs * 1024;
            float f0 = base[d2] + base[d2 + 512];
            float f1 = base[d2 + 1] + base[d2 + 513];
            ((__nv_bfloat162*)g_ctxs)[i] = __floats2bfloat162_rn(f0, f1);
        }
        for (int r = blk * 16 + warp; r < NV * 2048; r += GRID * 16) {
            int v = r / 2048, row = r % 2048;
            const float* wr = W_ih0 + (size_t)row * 1536;
            const float* ev = emb + v * 512;
            float s = 0.f;
            for (int i = lane; i < 512; i += 32) s += wr[i] * ev[i];
            for (int o = 16; o; o >>= 1) s += __shfl_xor_sync(0xffffffffu, s, o);
            if (!lane) g_E[v][row >> 9][row & 511] = s + b_ih0[row] + b_hh0[row];
        }
        int cb = blk;
#pragma unroll 1
        for (int r = 0; r < 16; r++) {
            int g = r & 3, jj = r >> 2;
            int row = g * 512 + cb * 4 + jj;
            for (int k = tid; k < 1536; k += NTHR) {
                float v = (k < 1024) ? W_ih0[(size_t)row * 1536 + 512 + k]
                                     : W_hh0[(size_t)row * 512 + (k - 1024)];
                smem[W1T_OFF + k * 16 + r] = v;
            }
            for (int k = tid; k < 1024; k += NTHR) {
                float v = (k < 512) ? W_ih1[(size_t)row * 512 + k]
                                    : W_hh1[(size_t)row * 512 + (k - 512)];
                smem[W2T_OFF + k * 16 + r] = v;
            }
        }
    }
    gbar();

    for (int t = 0; t <= NT; t++) {
        attn_phase(Wl, blv, out, t, blk, smem);
        if (t == NT) break;
        gbar();
        lstm1_phase(t, blk, smem);
        gbar();
        lstm2_phase(t, blk, smem);
        gbar();
    }

    if (out_size >= NB * NT * NV + NB * NT) {
        int i = blk * NTHR + tid;
        if (i < NB * NT) out[NB * NT * NV + i] = (float)tgt[i];
    }
}

// ---------------- launch ----------------
extern "C" void kernel_launch(void* const* d_in, const int* in_sizes, int n_in,
                              void* d_out, int out_size) {
    int off = (n_in >= 18) ? 0 : -1;
    const float* ctx   = (const float*)d_in[0];
    const int*   tgt   = (const int*)d_in[1];
    const float* h1_0  = (const float*)d_in[3 + off];
    const float* c1_0  = (const float*)d_in[4 + off];
    const float* h2_0  = (const float*)d_in[5 + off];
    const float* c2_0  = (const float*)d_in[6 + off];
    const float* emb   = (const float*)d_in[7 + off];
    const float* W_ih0 = (const float*)d_in[8 + off];
    const float* W_hh0 = (const float*)d_in[9 + off];
    const float* b_ih0 = (const float*)d_in[10 + off];
    const float* b_hh0 = (const float*)d_in[11 + off];
    const float* W_ih1 = (const float*)d_in[12 + off];
    const float* W_hh1 = (const float*)d_in[13 + off];
    const float* b_ih1 = (const float*)d_in[14 + off];
    const float* b_hh1 = (const float*)d_in[15 + off];
    const float* Wl    = (const float*)d_in[16 + off];
    const float* bl    = (const float*)d_in[17 + off];
    float* out = (float*)d_out;

    cudaFuncSetAttribute(k_persist, cudaFuncAttributeMaxDynamicSharedMemorySize, SMEM_BYTES);
    k_persist<<<GRID, NTHR, SMEM_BYTES>>>(ctx, tgt, h1_0, c1_0, h2_0, c2_0, emb,
                                          W_ih0, W_hh0, b_ih0, b_hh0,
                                          W_ih1, W_hh1, b_ih1, b_hh1,
                                          Wl, bl, out, out_size);
}

// round 13
// speedup vs baseline: 1.2406x; 1.2406x over previous
#include <cuda_runtime.h>
#include <cuda_bf16.h>

#define NB 64
#define NS 500
#define NH 512
#define NV 3
#define NT 500
#define GRID 128
#define NTHR 512

// ---- smem layout (floats) ----
#define W1T_OFF 0               // [1536][16]
#define W2T_OFF 24576           // [1024][16]
#define WORK_OFF 40960          // union: attn {sc,wts,pacc,red,red2,ctl} | lstm {xs[4],pt[3]}
#define SC_OFF   40960          // [256]
#define WTS_OFF  41216          // [256]
#define PACC_OFF 41472          // [256][4]
#define RED_OFF  42496          // [16]
#define RED2_OFF 42512          // [16]
#define CTL_OFF  42528          // [4]
#define XS_OFF   40960          // 4 x [32][64] = 8192
#define PT_OFF   49152          // 3 x [128][8] = 3072
#define H2_OFF  56320           // 512
#define S0_OFF  56832           // 64
#define S1_OFF  56896           // 64
#define LG_OFF  56960           // 4
#define SMEM_FLOATS 56964
#define SMEM_BYTES (SMEM_FLOATS * 4)

// ---------------- device state ----------------
__device__ __align__(16) __nv_bfloat16 g_ctxb[(size_t)NB * NS * 1024];  // 65.5 MB, L2-resident
__device__ __align__(16) float g_apart[2][NB][1024];
__device__ float g_m[NB][2];
__device__ float g_l[NB][2];
__device__ __align__(16) float g_h1[2][NB][NH];
__device__ __align__(16) float g_c1[NB][NH];
__device__ __align__(16) float g_h2[2][NB][NH];
__device__ __align__(16) float g_c2[NB][NH];
__device__ __align__(16) float g_E[NV][4][NH];
__device__ __align__(16) float g_B2[4][NH];
__device__ int g_idx[NB];

// tree barrier: monotonic counters (no reset races)
__device__ unsigned g_cnt1[8];
__device__ unsigned g_cnt2 = 0;
__device__ volatile unsigned g_epoch = 0;

__device__ __forceinline__ void gbar(int blk) {
    __syncthreads();                      // CTA writes happen-before tid0's fence
    if (threadIdx.x == 0) {
        __threadfence();
        unsigned e = g_epoch;
        if ((atomicAdd(&g_cnt1[blk >> 4], 1) & 15) == 15) {
            if ((atomicAdd(&g_cnt2, 1) & 7) == 7) {
                __threadfence();
                g_epoch = e + 1;
            }
        }
        if (g_epoch == e) {
            int it = 0;
            while (g_epoch == e) { if ((++it & 63) == 0) __nanosleep(64); }
        }
        __threadfence();
    }
    __syncthreads();
}

__device__ __forceinline__ float2 ffma2(float2 a, float2 b, float2 c) {
    float2 d;
    asm("fma.rn.f32x2 %0, %1, %2, %3;"
        : "=l"(*reinterpret_cast<unsigned long long*>(&d))
        : "l"(*reinterpret_cast<unsigned long long*>(&a)),
          "l"(*reinterpret_cast<unsigned long long*>(&b)),
          "l"(*reinterpret_cast<unsigned long long*>(&c)));
    return d;
}

__device__ __forceinline__ float sigm(float x) { return 1.f / (1.f + expf(-x)); }

__device__ __forceinline__ float2 bf2f(unsigned u) {
    float2 f;
    f.x = __uint_as_float(u << 16);
    f.y = __uint_as_float(u & 0xffff0000u);
    return f;
}

// dot of one full ctx row (4 x uint4 chunks) vs h2 (dims folded mod 512)
__device__ __forceinline__ float row_dot(uint4 u0, uint4 u1, uint4 u2, uint4 u3,
                                         float4 ha, float4 hb, float4 hc, float4 hd) {
    float s = 0.f; float2 p;
    p = bf2f(u0.x); s += p.x * ha.x + p.y * ha.y;
    p = bf2f(u0.y); s += p.x * ha.z + p.y * ha.w;
    p = bf2f(u0.z); s += p.x * hb.x + p.y * hb.y;
    p = bf2f(u0.w); s += p.x * hb.z + p.y * hb.w;
    p = bf2f(u1.x); s += p.x * hc.x + p.y * hc.y;
    p = bf2f(u1.y); s += p.x * hc.z + p.y * hc.w;
    p = bf2f(u1.z); s += p.x * hd.x + p.y * hd.y;
    p = bf2f(u1.w); s += p.x * hd.z + p.y * hd.w;
    p = bf2f(u2.x); s += p.x * ha.x + p.y * ha.y;
    p = bf2f(u2.y); s += p.x * ha.z + p.y * ha.w;
    p = bf2f(u2.z); s += p.x * hb.x + p.y * hb.y;
    p = bf2f(u2.w); s += p.x * hb.z + p.y * hb.w;
    p = bf2f(u3.x); s += p.x * hc.x + p.y * hc.y;
    p = bf2f(u3.y); s += p.x * hc.z + p.y * hc.w;
    p = bf2f(u3.z); s += p.x * hd.x + p.y * hd.y;
    p = bf2f(u3.w); s += p.x * hd.z + p.y * hd.w;
    return s;
}

// ---------------- attention: direct-L2, 3-pass ----------------
__device__ void attn_phase(const float* __restrict__ Wl,
                           const float* __restrict__ blv, float* __restrict__ out,
                           int t, int blk, float* smem) {
    int p = t & 1;
    int b = blk >> 1, h = blk & 1;
    int tid = threadIdx.x;
    int warp = tid >> 5, lane = tid & 31;
    float* h2s  = smem + H2_OFF;
    float* sc   = smem + SC_OFF;
    float* wts  = smem + WTS_OFF;
    float* pacc = smem + PACC_OFF;
    float* red  = smem + RED_OFF;
    float* red2 = smem + RED2_OFF;
    float* ctl  = smem + CTL_OFF;
    float* lg   = smem + LG_OFF;

    const float* h2g = g_h2[p][b];
    h2s[tid] = h2g[tid];

    // ---- logits / argmax / log_softmax for step t-1 (both halves compute; h==0 stores) ----
    if (t > 0) {
        if (warp < 3) {
            const float* wr = Wl + warp * 512;
            float s = 0.f;
            for (int i = lane; i < 512; i += 32) s += wr[i] * h2g[i];
            for (int o = 16; o; o >>= 1) s += __shfl_xor_sync(0xffffffffu, s, o);
            if (!lane) lg[warp] = s + blv[warp];
        }
        __syncthreads();
        if (tid == 0) {
            float l0 = lg[0], l1 = lg[1], l2 = lg[2];
            int bi = 0; float bv = l0;
            if (l1 > bv) { bv = l1; bi = 1; }
            if (l2 > bv) { bv = l2; bi = 2; }
            float lse = bv + logf(expf(l0 - bv) + expf(l1 - bv) + expf(l2 - bv));
            if (h == 0) {
                g_idx[b] = bi;
                float* o = out + ((size_t)b * NT + (t - 1)) * 3;
                o[0] = l0 - lse; o[1] = l1 - lse; o[2] = l2 - lse;
            }
        }
    }
    if (t >= NT) return;
    __syncthreads();   // h2s ready

    const __nv_bfloat16* gbase = g_ctxb + ((size_t)(b * NS + h * 250)) * 1024;

    // ---- pass A: scores. warp w: rows w, w+16, ... (2-row ILP) ----
    {
        float4 ha = ((const float4*)h2s)[2 * lane];
        float4 hb = ((const float4*)h2s)[2 * lane + 1];
        float4 hc = ((const float4*)h2s)[64 + 2 * lane];
        float4 hd = ((const float4*)h2s)[64 + 2 * lane + 1];
        const uint4 z4 = make_uint4(0, 0, 0, 0);
#pragma unroll
        for (int i = 0; i < 16; i += 2) {
            int r0 = warp + 16 * i;
            int r1 = r0 + 16;
            bool v0 = r0 < 250, v1 = r1 < 250;
            const uint4* rp0 = (const uint4*)(gbase + (size_t)r0 * 1024);
            const uint4* rp1 = (const uint4*)(gbase + (size_t)r1 * 1024);
            uint4 A0 = z4, A1 = z4, A2 = z4, A3 = z4;
            uint4 B0 = z4, B1 = z4, B2 = z4, B3 = z4;
            if (v0) { A0 = rp0[lane]; A1 = rp0[32 + lane]; A2 = rp0[64 + lane]; A3 = rp0[96 + lane]; }
            if (v1) { B0 = rp1[lane]; B1 = rp1[32 + lane]; B2 = rp1[64 + lane]; B3 = rp1[96 + lane]; }
            float s0 = row_dot(A0, A1, A2, A3, ha, hb, hc, hd);
            float s1 = row_dot(B0, B1, B2, B3, ha, hb, hc, hd);
            for (int o = 16; o; o >>= 1) {
                s0 += __shfl_xor_sync(0xffffffffu, s0, o);
                s1 += __shfl_xor_sync(0xffffffffu, s1, o);
            }
            if (!lane) {
                if (v0) sc[r0] = s0;
                if (v1) sc[r1] = s1;
            }
        }
    }
    __syncthreads();

    // ---- pass B: softmax stats ----
    {
        float v = (tid < 250) ? sc[tid] : -1e30f;
        float mv = v;
        for (int o = 16; o; o >>= 1) mv = fmaxf(mv, __shfl_xor_sync(0xffffffffu, mv, o));
        if (!lane) red[warp] = mv;
    }
    __syncthreads();
    if (warp == 0) {
        float mv = (lane < 16) ? red[lane] : -1e30f;
        for (int o = 8; o; o >>= 1) mv = fmaxf(mv, __shfl_xor_sync(0xffffffffu, mv, o));
        if (!lane) ctl[0] = mv;
    }
    __syncthreads();
    {
        float m = ctl[0];
        float w = (tid < 250) ? __expf(sc[tid] - m) : 0.f;
        if (tid < 250) wts[tid] = w;
        for (int o = 16; o; o >>= 1) w += __shfl_xor_sync(0xffffffffu, w, o);
        if (!lane) red2[warp] = w;
    }
    __syncthreads();

    // ---- pass C: accumulate. group g rows [125g,125g+125), thread owns 4 dims, 2-row ILP ----
    {
        int g = tid >> 8, tl = tid & 255;
        const __nv_bfloat16* base2 = gbase + 4 * tl + (size_t)(g * 125) * 1024;
        float4 acc0 = make_float4(0.f, 0.f, 0.f, 0.f);
        float4 acc1 = make_float4(0.f, 0.f, 0.f, 0.f);
        const float* wp2 = wts + g * 125;
#pragma unroll 6
        for (int r = 0; r < 124; r += 2) {
            float w0 = wp2[r], w1 = wp2[r + 1];
            uint2 q0 = *(const uint2*)(base2 + (size_t)r * 1024);
            uint2 q1 = *(const uint2*)(base2 + (size_t)(r + 1) * 1024);
            float2 a0 = bf2f(q0.x), a1 = bf2f(q0.y);
            float2 b0 = bf2f(q1.x), b1 = bf2f(q1.y);
            acc0.x += w0 * a0.x; acc0.y += w0 * a0.y;
            acc0.z += w0 * a1.x; acc0.w += w0 * a1.y;
            acc1.x += w1 * b0.x; acc1.y += w1 * b0.y;
            acc1.z += w1 * b1.x; acc1.w += w1 * b1.y;
        }
        {
            float w0 = wp2[124];
            uint2 q0 = *(const uint2*)(base2 + (size_t)124 * 1024);
            float2 a0 = bf2f(q0.x), a1 = bf2f(q0.y);
            acc0.x += w0 * a0.x; acc0.y += w0 * a0.y;
            acc0.z += w0 * a1.x; acc0.w += w0 * a1.y;
        }
        float4 acc = make_float4(acc0.x + acc1.x, acc0.y + acc1.y,
                                 acc0.z + acc1.z, acc0.w + acc1.w);
        if (g == 1) ((float4*)pacc)[tl] = acc;
        __syncthreads();
        if (g == 0) {
            float4 o = ((float4*)pacc)[tl];
            acc.x += o.x; acc.y += o.y; acc.z += o.z; acc.w += o.w;
            ((float4*)g_apart[h][b])[tl] = acc;
            if (tl == 0) {
                g_m[b][h] = ctl[0];
                float l = 0.f;
#pragma unroll
                for (int i = 0; i < 16; i++) l += red2[i];
                g_l[b][h] = l;
            }
        }
    }
}

// ---------------- LSTM 1: 4-way split-K, register-pipelined x ----------------
__device__ void lstm1_phase(int t, int cb, float* smem) {
    int p = t & 1, q = p ^ 1;
    int tid = threadIdx.x;
    int quar = tid >> 7, tl = tid & 127;
    int b = tl & 63, jj = tl >> 6;
    float* s0s = smem + S0_OFF;
    float* s1s = smem + S1_OFF;
    float* xsq = smem + XS_OFF + quar * 2048;
    const float4* wp = (const float4*)(smem + W1T_OFF);

    if (tid < 64) {
        float m0 = g_m[tid][0], m1 = g_m[tid][1];
        float M = fmaxf(m0, m1);
        float e0 = __expf(m0 - M), e1 = __expf(m1 - M);
        float L = g_l[tid][0] * e0 + g_l[tid][1] * e1;
        s0s[tid] = e0 / L; s1s[tid] = e1 / L;
    }

    int jc0 = cb * 4 + jj, jc1 = jc0 + 2;
    float2 A0g01, A0g23, A1g01, A1g23;
    if (quar == 0) {
        int vv = g_idx[b];
        A0g01 = make_float2(g_E[vv][0][jc0], g_E[vv][1][jc0]);
        A0g23 = make_float2(g_E[vv][2][jc0], g_E[vv][3][jc0]);
        A1g01 = make_float2(g_E[vv][0][jc1], g_E[vv][1][jc1]);
        A1g23 = make_float2(g_E[vv][2][jc1], g_E[vv][3][jc1]);
    } else {
        A0g01 = make_float2(0.f, 0.f); A0g23 = make_float2(0.f, 0.f);
        A1g01 = make_float2(0.f, 0.f); A1g23 = make_float2(0.f, 0.f);
    }

    int bq = tl >> 1;
    int kh = (tl & 1) * 16;
    int kbase = quar * 384;

    float4 xa0, xa1, xa2, xa3, xb0, xb1, xb2, xb3;
    xb0 = xb1 = xb2 = xb3 = make_float4(0.f, 0.f, 0.f, 0.f);
    {   // preload kt=0
        int k0 = kbase + kh;
        if (k0 < 1024) {
            xa0 = *(const float4*)&g_apart[0][bq][k0];
            xa1 = *(const float4*)&g_apart[0][bq][k0 + 4];
            xa2 = *(const float4*)&g_apart[0][bq][k0 + 8];
            xa3 = *(const float4*)&g_apart[0][bq][k0 + 12];
            xb0 = *(const float4*)&g_apart[1][bq][k0];
            xb1 = *(const float4*)&g_apart[1][bq][k0 + 4];
            xb2 = *(const float4*)&g_apart[1][bq][k0 + 8];
            xb3 = *(const float4*)&g_apart[1][bq][k0 + 12];
        } else {
            xa0 = *(const float4*)&g_h1[p][bq][k0 - 1024];
            xa1 = *(const float4*)&g_h1[p][bq][k0 - 1020];
            xa2 = *(const float4*)&g_h1[p][bq][k0 - 1016];
            xa3 = *(const float4*)&g_h1[p][bq][k0 - 1012];
        }
    }

    for (int kt = 0; kt < 12; kt++) {
        int kb = kbase + kt * 32;
        __syncthreads();   // xs free (first iter: also orders s0s)
        int k0 = kb + kh;
        if (k0 < 1024) {
            float s0v = s0s[bq], s1v = s1s[bq];
            xsq[(kh + 0) * 64 + bq]  = s0v * xa0.x + s1v * xb0.x;
            xsq[(kh + 1) * 64 + bq]  = s0v * xa0.y + s1v * xb0.y;
            xsq[(kh + 2) * 64 + bq]  = s0v * xa0.z + s1v * xb0.z;
            xsq[(kh + 3) * 64 + bq]  = s0v * xa0.w + s1v * xb0.w;
            xsq[(kh + 4) * 64 + bq]  = s0v * xa1.x + s1v * xb1.x;
            xsq[(kh + 5) * 64 + bq]  = s0v * xa1.y + s1v * xb1.y;
            xsq[(kh + 6) * 64 + bq]  = s0v * xa1.z + s1v * xb1.z;
            xsq[(kh + 7) * 64 + bq]  = s0v * xa1.w + s1v * xb1.w;
            xsq[(kh + 8) * 64 + bq]  = s0v * xa2.x + s1v * xb2.x;
            xsq[(kh + 9) * 64 + bq]  = s0v * xa2.y + s1v * xb2.y;
            xsq[(kh + 10) * 64 + bq] = s0v * xa2.z + s1v * xb2.z;
            xsq[(kh + 11) * 64 + bq] = s0v * xa2.w + s1v * xb2.w;
            xsq[(kh + 12) * 64 + bq] = s0v * xa3.x + s1v * xb3.x;
            xsq[(kh + 13) * 64 + bq] = s0v * xa3.y + s1v * xb3.y;
            xsq[(kh + 14) * 64 + bq] = s0v * xa3.z + s1v * xb3.z;
            xsq[(kh + 15) * 64 + bq] = s0v * xa3.w + s1v * xb3.w;
        } else {
            xsq[(kh + 0) * 64 + bq]  = xa0.x; xsq[(kh + 1) * 64 + bq]  = xa0.y;
            xsq[(kh + 2) * 64 + bq]  = xa0.z; xsq[(kh + 3) * 64 + bq]  = xa0.w;
            xsq[(kh + 4) * 64 + bq]  = xa1.x; xsq[(kh + 5) * 64 + bq]  = xa1.y;
            xsq[(kh + 6) * 64 + bq]  = xa1.z; xsq[(kh + 7) * 64 + bq]  = xa1.w;
            xsq[(kh + 8) * 64 + bq]  = xa2.x; xsq[(kh + 9) * 64 + bq]  = xa2.y;
            xsq[(kh + 10) * 64 + bq] = xa2.z; xsq[(kh + 11) * 64 + bq] = xa2.w;
            xsq[(kh + 12) * 64 + bq] = xa3.x; xsq[(kh + 13) * 64 + bq] = xa3.y;
            xsq[(kh + 14) * 64 + bq] = xa3.z; xsq[(kh + 15) * 64 + bq] = xa3.w;
        }
        if (kt + 1 < 12) {   // preload next tile (latency hidden under FMA loop)
            int kn = kbase + (kt + 1) * 32 + kh;
            if (kn < 1024) {
                xa0 = *(const float4*)&g_apart[0][bq][kn];
                xa1 = *(const float4*)&g_apart[0][bq][kn + 4];
                xa2 = *(const float4*)&g_apart[0][bq][kn + 8];
                xa3 = *(const float4*)&g_apart[0][bq][kn + 12];
                xb0 = *(const float4*)&g_apart[1][bq][kn];
                xb1 = *(const float4*)&g_apart[1][bq][kn + 4];
                xb2 = *(const float4*)&g_apart[1][bq][kn + 8];
                xb3 = *(const float4*)&g_apart[1][bq][kn + 12];
            } else {
                xa0 = *(const float4*)&g_h1[p][bq][kn - 1024];
                xa1 = *(const float4*)&g_h1[p][bq][kn - 1020];
                xa2 = *(const float4*)&g_h1[p][bq][kn - 1016];
                xa3 = *(const float4*)&g_h1[p][bq][kn - 1012];
            }
        }
        __syncthreads();   // xs ready
#pragma unroll
        for (int k = 0; k < 32; k++) {
            float x = xsq[k * 64 + b];
            float4 w0 = wp[(kb + k) * 4 + jj];
            float4 w1 = wp[(kb + k) * 4 + jj + 2];
            float2 xx = make_float2(x, x);
            A0g01 = ffma2(make_float2(w0.x, w0.y), xx, A0g01);
            A0g23 = ffma2(make_float2(w0.z, w0.w), xx, A0g23);
            A1g01 = ffma2(make_float2(w1.x, w1.y), xx, A1g01);
            A1g23 = ffma2(make_float2(w1.z, w1.w), xx, A1g23);
        }
    }
    if (quar) {
        float4* dst = (float4*)(smem + PT_OFF + (quar - 1) * 1024);
        dst[tl * 2]     = make_float4(A0g01.x, A0g01.y, A0g23.x, A0g23.y);
        dst[tl * 2 + 1] = make_float4(A1g01.x, A1g01.y, A1g23.x, A1g23.y);
    }
    __syncthreads();
    if (quar == 0) {
        const float4* p1 = (const float4*)(smem + PT_OFF);
        const float4* p2 = (const float4*)(smem + PT_OFF + 1024);
        const float4* p3 = (const float4*)(smem + PT_OFF + 2048);
        float4 u = p1[tl * 2], v = p2[tl * 2], w = p3[tl * 2];
        float4 a = make_float4(A0g01.x + u.x + v.x + w.x, A0g01.y + u.y + v.y + w.y,
                               A0g23.x + u.z + v.z + w.z, A0g23.y + u.w + v.w + w.w);
        float si = sigm(a.x), sf = sigm(a.y), so = sigm(a.w);
        float tg = tanhf(a.z);
        float cn = sf * g_c1[b][jc0] + si * tg;
        g_c1[b][jc0] = cn;
        g_h1[q][b][jc0] = so * tanhf(cn);
        u = p1[tl * 2 + 1]; v = p2[tl * 2 + 1]; w = p3[tl * 2 + 1];
        a = make_float4(A1g01.x + u.x + v.x + w.x, A1g01.y + u.y + v.y + w.y,
                        A1g23.x + u.z + v.z + w.z, A1g23.y + u.w + v.w + w.w);
        si = sigm(a.x); sf = sigm(a.y); so = sigm(a.w);
        tg = tanhf(a.z);
        cn = sf * g_c1[b][jc1] + si * tg;
        g_c1[b][jc1] = cn;
        g_h1[q][b][jc1] = so * tanhf(cn);
    }
}

// ---------------- LSTM 2: 4-way split-K, register-pipelined x ----------------
__device__ void lstm2_phase(int t, int cb, float* smem) {
    int p = t & 1, q = p ^ 1;
    int tid = threadIdx.x;
    int quar = tid >> 7, tl = tid & 127;
    int b = tl & 63, jj = tl >> 6;
    float* xsq = smem + XS_OFF + quar * 2048;
    const float4* wp = (const float4*)(smem + W2T_OFF);

    int jc0 = cb * 4 + jj, jc1 = jc0 + 2;
    float2 A0g01, A0g23, A1g01, A1g23;
    if (quar == 0) {
        A0g01 = make_float2(g_B2[0][jc0], g_B2[1][jc0]);
        A0g23 = make_float2(g_B2[2][jc0], g_B2[3][jc0]);
        A1g01 = make_float2(g_B2[0][jc1], g_B2[1][jc1]);
        A1g23 = make_float2(g_B2[2][jc1], g_B2[3][jc1]);
    } else {
        A0g01 = make_float2(0.f, 0.f); A0g23 = make_float2(0.f, 0.f);
        A1g01 = make_float2(0.f, 0.f); A1g23 = make_float2(0.f, 0.f);
    }

    int bq = tl >> 1;
    int kh = (tl & 1) * 16;
    int kbase = quar * 256;

    float4 xa0, xa1, xa2, xa3;
    {
        int k0 = kbase + kh;
        const float* src = (k0 < 512) ? &g_h1[q][bq][k0] : &g_h2[p][bq][k0 - 512];
        xa0 = *(const float4*)src;
        xa1 = *(const float4*)(src + 4);
        xa2 = *(const float4*)(src + 8);
        xa3 = *(const float4*)(src + 12);
    }

    for (int kt = 0; kt < 8; kt++) {
        int kb = kbase + kt * 32;
        __syncthreads();
        xsq[(kh + 0) * 64 + bq]  = xa0.x; xsq[(kh + 1) * 64 + bq]  = xa0.y;
        xsq[(kh + 2) * 64 + bq]  = xa0.z; xsq[(kh + 3) * 64 + bq]  = xa0.w;
        xsq[(kh + 4) * 64 + bq]  = xa1.x; xsq[(kh + 5) * 64 + bq]  = xa1.y;
        xsq[(kh + 6) * 64 + bq]  = xa1.z; xsq[(kh + 7) * 64 + bq]  = xa1.w;
        xsq[(kh + 8) * 64 + bq]  = xa2.x; xsq[(kh + 9) * 64 + bq]  = xa2.y;
        xsq[(kh + 10) * 64 + bq] = xa2.z; xsq[(kh + 11) * 64 + bq] = xa2.w;
        xsq[(kh + 12) * 64 + bq] = xa3.x; xsq[(kh + 13) * 64 + bq] = xa3.y;
        xsq[(kh + 14) * 64 + bq] = xa3.z; xsq[(kh + 15) * 64 + bq] = xa3.w;
        if (kt + 1 < 8) {
            int kn = kbase + (kt + 1) * 32 + kh;
            const float* src = (kn < 512) ? &g_h1[q][bq][kn] : &g_h2[p][bq][kn - 512];
            xa0 = *(const float4*)src;
            xa1 = *(const float4*)(src + 4);
            xa2 = *(const float4*)(src + 8);
            xa3 = *(const float4*)(src + 12);
        }
        __syncthreads();
#pragma unroll
        for (int k = 0; k < 32; k++) {
            float x = xsq[k * 64 + b];
            float4 w0 = wp[(kb + k) * 4 + jj];
            float4 w1 = wp[(kb + k) * 4 + jj + 2];
            float2 xx = make_float2(x, x);
            A0g01 = ffma2(make_float2(w0.x, w0.y), xx, A0g01);
            A0g23 = ffma2(make_float2(w0.z, w0.w), xx, A0g23);
            A1g01 = ffma2(make_float2(w1.x, w1.y), xx, A1g01);
            A1g23 = ffma2(make_float2(w1.z, w1.w), xx, A1g23);
        }
    }
    if (quar) {
        float4* dst = (float4*)(smem + PT_OFF + (quar - 1) * 1024);
        dst[tl * 2]     = make_float4(A0g01.x, A0g01.y, A0g23.x, A0g23.y);
        dst[tl * 2 + 1] = make_float4(A1g01.x, A1g01.y, A1g23.x, A1g23.y);
    }
    __syncthreads();
    if (quar == 0) {
        const float4* p1 = (const float4*)(smem + PT_OFF);
        const float4* p2 = (const float4*)(smem + PT_OFF + 1024);
        const float4* p3 = (const float4*)(smem + PT_OFF + 2048);
        float4 u = p1[tl * 2], v = p2[tl * 2], w = p3[tl * 2];
        float4 a = make_float4(A0g01.x + u.x + v.x + w.x, A0g01.y + u.y + v.y + w.y,
                               A0g23.x + u.z + v.z + w.z, A0g23.y + u.w + v.w + w.w);
        float si = sigm(a.x), sf = sigm(a.y), so = sigm(a.w);
        float tg = tanhf(a.z);
        float cn = sf * g_c2[b][jc0] + si * tg;
        g_c2[b][jc0] = cn;
        g_h2[q][b][jc0] = so * tanhf(cn);
        u = p1[tl * 2 + 1]; v = p2[tl * 2 + 1]; w = p3[tl * 2 + 1];
        a = make_float4(A1g01.x + u.x + v.x + w.x, A1g01.y + u.y + v.y + w.y,
                        A1g23.x + u.z + v.z + w.z, A1g23.y + u.w + v.w + w.w);
        si = sigm(a.x); sf = sigm(a.y); so = sigm(a.w);
        tg = tanhf(a.z);
        cn = sf * g_c2[b][jc1] + si * tg;
        g_c2[b][jc1] = cn;
        g_h2[q][b][jc1] = so * tanhf(cn);
    }
}

// ---------------- persistent kernel ----------------
__global__ void __launch_bounds__(NTHR, 1)
k_persist(const float* __restrict__ ctx, const int* __restrict__ tgt,
          const float* __restrict__ h1_0, const float* __restrict__ c1_0,
          const float* __restrict__ h2_0, const float* __restrict__ c2_0,
          const float* __restrict__ emb,
          const float* __restrict__ W_ih0, const float* __restrict__ W_hh0,
          const float* __restrict__ b_ih0, const float* __restrict__ b_hh0,
          const float* __restrict__ W_ih1, const float* __restrict__ W_hh1,
          const float* __restrict__ b_ih1, const float* __restrict__ b_hh1,
          const float* __restrict__ Wl, const float* __restrict__ blv,
          float* __restrict__ out, int out_size) {
    extern __shared__ __align__(16) float smem[];
    int blk = blockIdx.x;
    int tid = threadIdx.x;
    int warp = tid >> 5, lane = tid & 31;

    // ---- setup ----
    {
        int gi = blk * NTHR + tid;
        if (gi < NB * NH) {
            ((float*)g_h1[0])[gi] = h1_0[gi];
            ((float*)g_c1)[gi]    = c1_0[gi];
            ((float*)g_h2[0])[gi] = h2_0[gi];
            ((float*)g_c2)[gi]    = c2_0[gi];
        }
        if (gi < 4 * NH) ((float*)g_B2)[gi] = b_ih1[gi] + b_hh1[gi];
        if (blk == 0 && tid < NB) g_idx[tid] = tgt[tid * NT];
        // fp32 ctx -> bf16 copy (L2-resident working set)
        for (int i = gi; i < NB * NS * 512; i += GRID * NTHR) {
            float2 v = ((const float2*)ctx)[i];
            ((__nv_bfloat162*)g_ctxb)[i] = __floats2bfloat162_rn(v.x, v.y);
        }
        for (int r = blk * 16 + warp; r < NV * 2048; r += GRID * 16) {
            int v = r / 2048, row = r % 2048;
            const float* wr = W_ih0 + (size_t)row * 1536;
            const float* ev = emb + v * 512;
            float s = 0.f;
            for (int i = lane; i < 512; i += 32) s += wr[i] * ev[i];
            for (int o = 16; o; o >>= 1) s += __shfl_xor_sync(0xffffffffu, s, o);
            if (!lane) g_E[v][row >> 9][row & 511] = s + b_ih0[row] + b_hh0[row];
        }
        int cb = blk;
#pragma unroll 1
        for (int r = 0; r < 16; r++) {
            int g = r & 3, jj = r >> 2;
            int row = g * 512 + cb * 4 + jj;
            for (int k = tid; k < 1536; k += NTHR) {
                float v = (k < 1024) ? W_ih0[(size_t)row * 1536 + 512 + k]
                                     : W_hh0[(size_t)row * 512 + (k - 1024)];
                smem[W1T_OFF + k * 16 + r] = v;
            }
            for (int k = tid; k < 1024; k += NTHR) {
                float v = (k < 512) ? W_ih1[(size_t)row * 512 + k]
                                    : W_hh1[(size_t)row * 512 + (k - 512)];
                smem[W2T_OFF + k * 16 + r] = v;
            }
        }
    }
    gbar(blk);

    for (int t = 0; t <= NT; t++) {
        attn_phase(Wl, blv, out, t, blk, smem);
        if (t == NT) break;
        gbar(blk);
        lstm1_phase(t, blk, smem);
        gbar(blk);
        lstm2_phase(t, blk, smem);
        gbar(blk);
    }

    if (out_size >= NB * NT * NV + NB * NT) {
        int i = blk * NTHR + tid;
        if (i < NB * NT) out[NB * NT * NV + i] = (float)tgt[i];
    }
}

// ---------------- launch ----------------
extern "C" void kernel_launch(void* const* d_in, const int* in_sizes, int n_in,
                              void* d_out, int out_size) {
    int off = (n_in >= 18) ? 0 : -1;
    const float* ctx   = (const float*)d_in[0];
    const int*   tgt   = (const int*)d_in[1];
    const float* h1_0  = (const float*)d_in[3 + off];
    const float* c1_0  = (const float*)d_in[4 + off];
    const float* h2_0  = (const float*)d_in[5 + off];
    const float* c2_0  = (const float*)d_in[6 + off];
    const float* emb   = (const float*)d_in[7 + off];
    const float* W_ih0 = (const float*)d_in[8 + off];
    const float* W_hh0 = (const float*)d_in[9 + off];
    const float* b_ih0 = (const float*)d_in[10 + off];
    const float* b_hh0 = (const float*)d_in[11 + off];
    const float* W_ih1 = (const float*)d_in[12 + off];
    const float* W_hh1 = (const float*)d_in[13 + off];
    const float* b_ih1 = (const float*)d_in[14 + off];
    const float* b_hh1 = (const float*)d_in[15 + off];
    const float* Wl    = (const float*)d_in[16 + off];
    const float* bl    = (const float*)d_in[17 + off];
    float* out = (float*)d_out;

    cudaFuncSetAttribute(k_persist, cudaFuncAttributeMaxDynamicSharedMemorySize, SMEM_BYTES);
    k_persist<<<GRID, NTHR, SMEM_BYTES>>>(ctx, tgt, h1_0, c1_0, h2_0, c2_0, emb,
                                          W_ih0, W_hh0, b_ih0, b_hh0,
                                          W_ih1, W_hh1, b_ih1, b_hh1,
                                          Wl, bl, out, out_size);
}

// round 17
// speedup vs baseline: 1.2514x; 1.0087x over previous
#include <cuda_runtime.h>
#include <cuda_bf16.h>

#define NB 64
#define NS 500
#define NH 512
#define NV 3
#define NT 500
#define GRID 128
#define NTHR 512

// ---- smem layout (floats) ----
#define W1T_OFF 0               // [1536][16]
#define W2T_OFF 24576           // [1024][16]
#define WORK_OFF 40960          // union: attn {sc,wts,pacc,red,red2,ctl} | lstm {xs[4],pt[3]}
#define SC_OFF   40960          // [256]
#define WTS_OFF  41216          // [256]
#define PACC_OFF 41472          // [256][4]
#define RED_OFF  42496          // [16]
#define RED2_OFF 42512          // [16]
#define CTL_OFF  42528          // [4]
#define XS_OFF   40960          // 4 x [32][64] = 8192
#define PT_OFF   49152          // 3 x [128][8] = 3072
#define H2_OFF  52224           // 512
#define LG_OFF  52736           // 4
#define SMEM_FLOATS 52740
#define SMEM_BYTES (SMEM_FLOATS * 4)

// per-quarter named barrier (warps of a quarter are contiguous: 128 threads)
#define QBAR(q) asm volatile("bar.sync %0, 128;" :: "r"((q) + 1) : "memory")

// ---------------- device state ----------------
__device__ __align__(16) __nv_bfloat16 g_ctxb[(size_t)NB * NS * 1024];  // 65.5 MB, L2-resident
__device__ __align__(16) float g_apart[2][NB][1024];
__device__ float g_m[NB][2];
__device__ float g_l[NB][2];
__device__ __align__(16) float g_h1[2][NB][NH];
__device__ __align__(16) float g_c1[NB][NH];
__device__ __align__(16) float g_h2[2][NB][NH];
__device__ __align__(16) float g_c2[NB][NH];
__device__ __align__(16) float g_E[NV][4][NH];
__device__ __align__(16) float g_B2[4][NH];
__device__ int g_idx[NB];

// tree barrier: monotonic counters (no reset races)
__device__ unsigned g_cnt1[8];
__device__ unsigned g_cnt2 = 0;
__device__ volatile unsigned g_epoch = 0;

__device__ __forceinline__ void gbar(int blk) {
    __syncthreads();
    if (threadIdx.x == 0) {
        __threadfence();
        unsigned e = g_epoch;
        if ((atomicAdd(&g_cnt1[blk >> 4], 1) & 15) == 15) {
            if ((atomicAdd(&g_cnt2, 1) & 7) == 7) {
                __threadfence();
                g_epoch = e + 1;
            }
        }
        if (g_epoch == e) {
            int it = 0;
            while (g_epoch == e) { if ((++it & 63) == 0) __nanosleep(64); }
        }
        __threadfence();
    }
    __syncthreads();
}

__device__ __forceinline__ float2 ffma2(float2 a, float2 b, float2 c) {
    float2 d;
    asm("fma.rn.f32x2 %0, %1, %2, %3;"
        : "=l"(*reinterpret_cast<unsigned long long*>(&d))
        : "l"(*reinterpret_cast<unsigned long long*>(&a)),
          "l"(*reinterpret_cast<unsigned long long*>(&b)),
          "l"(*reinterpret_cast<unsigned long long*>(&c)));
    return d;
}

__device__ __forceinline__ float sigm(float x) { return 1.f / (1.f + expf(-x)); }

__device__ __forceinline__ float2 bf2f(unsigned u) {
    float2 f;
    f.x = __uint_as_float(u << 16);
    f.y = __uint_as_float(u & 0xffff0000u);
    return f;
}

// dot of one full ctx row (4 x uint4 chunks) vs h2 (dims folded mod 512)
__device__ __forceinline__ float row_dot(uint4 u0, uint4 u1, uint4 u2, uint4 u3,
                                         float4 ha, float4 hb, float4 hc, float4 hd) {
    float s = 0.f; float2 p;
    p = bf2f(u0.x); s += p.x * ha.x + p.y * ha.y;
    p = bf2f(u0.y); s += p.x * ha.z + p.y * ha.w;
    p = bf2f(u0.z); s += p.x * hb.x + p.y * hb.y;
    p = bf2f(u0.w); s += p.x * hb.z + p.y * hb.w;
    p = bf2f(u1.x); s += p.x * hc.x + p.y * hc.y;
    p = bf2f(u1.y); s += p.x * hc.z + p.y * hc.w;
    p = bf2f(u1.z); s += p.x * hd.x + p.y * hd.y;
    p = bf2f(u1.w); s += p.x * hd.z + p.y * hd.w;
    p = bf2f(u2.x); s += p.x * ha.x + p.y * ha.y;
    p = bf2f(u2.y); s += p.x * ha.z + p.y * ha.w;
    p = bf2f(u2.z); s += p.x * hb.x + p.y * hb.y;
    p = bf2f(u2.w); s += p.x * hb.z + p.y * hb.w;
    p = bf2f(u3.x); s += p.x * hc.x + p.y * hc.y;
    p = bf2f(u3.y); s += p.x * hc.z + p.y * hc.w;
    p = bf2f(u3.z); s += p.x * hd.x + p.y * hd.y;
    p = bf2f(u3.w); s += p.x * hd.z + p.y * hd.w;
    return s;
}

// ---------------- attention: direct-L2, 3-pass, fused pass-A max ----------------
__device__ void attn_phase(const float* __restrict__ Wl,
                           const float* __restrict__ blv, float* __restrict__ out,
                           int t, int blk, float* smem) {
    int p = t & 1;
    int b = blk >> 1, h = blk & 1;
    int tid = threadIdx.x;
    int warp = tid >> 5, lane = tid & 31;
    float* h2s  = smem + H2_OFF;
    float* sc   = smem + SC_OFF;
    float* wts  = smem + WTS_OFF;
    float* pacc = smem + PACC_OFF;
    float* red  = smem + RED_OFF;
    float* red2 = smem + RED2_OFF;
    float* ctl  = smem + CTL_OFF;
    float* lg   = smem + LG_OFF;

    const float* h2g = g_h2[p][b];
    h2s[tid] = h2g[tid];

    // ---- logits / argmax / log_softmax for step t-1 (both halves compute; h==0 stores) ----
    if (t > 0) {
        if (warp < 3) {
            const float* wr = Wl + warp * 512;
            float s = 0.f;
            for (int i = lane; i < 512; i += 32) s += wr[i] * h2g[i];
            for (int o = 16; o; o >>= 1) s += __shfl_xor_sync(0xffffffffu, s, o);
            if (!lane) lg[warp] = s + blv[warp];
        }
        __syncthreads();
        if (tid == 0) {
            float l0 = lg[0], l1 = lg[1], l2 = lg[2];
            int bi = 0; float bv = l0;
            if (l1 > bv) { bv = l1; bi = 1; }
            if (l2 > bv) { bv = l2; bi = 2; }
            float lse = bv + logf(expf(l0 - bv) + expf(l1 - bv) + expf(l2 - bv));
            if (h == 0) {
                g_idx[b] = bi;
                float* o = out + ((size_t)b * NT + (t - 1)) * 3;
                o[0] = l0 - lse; o[1] = l1 - lse; o[2] = l2 - lse;
            }
        }
    }
    if (t >= NT) return;
    __syncthreads();   // h2s ready

    const __nv_bfloat16* gbase = g_ctxb + ((size_t)(b * NS + h * 250)) * 1024;

    // ---- pass A: scores + per-warp running max. warp w: rows w, w+16, ... ----
    {
        float4 ha = ((const float4*)h2s)[2 * lane];
        float4 hb = ((const float4*)h2s)[2 * lane + 1];
        float4 hc = ((const float4*)h2s)[64 + 2 * lane];
        float4 hd = ((const float4*)h2s)[64 + 2 * lane + 1];
        const uint4 z4 = make_uint4(0, 0, 0, 0);
        float wmax = -1e30f;
#pragma unroll
        for (int i = 0; i < 16; i += 2) {
            int r0 = warp + 16 * i;
            int r1 = r0 + 16;
            bool v0 = r0 < 250, v1 = r1 < 250;
            const uint4* rp0 = (const uint4*)(gbase + (size_t)r0 * 1024);
            const uint4* rp1 = (const uint4*)(gbase + (size_t)r1 * 1024);
            uint4 A0 = z4, A1 = z4, A2 = z4, A3 = z4;
            uint4 B0 = z4, B1 = z4, B2 = z4, B3 = z4;
            if (v0) { A0 = rp0[lane]; A1 = rp0[32 + lane]; A2 = rp0[64 + lane]; A3 = rp0[96 + lane]; }
            if (v1) { B0 = rp1[lane]; B1 = rp1[32 + lane]; B2 = rp1[64 + lane]; B3 = rp1[96 + lane]; }
            float s0 = row_dot(A0, A1, A2, A3, ha, hb, hc, hd);
            float s1 = row_dot(B0, B1, B2, B3, ha, hb, hc, hd);
            for (int o = 16; o; o >>= 1) {
                s0 += __shfl_xor_sync(0xffffffffu, s0, o);
                s1 += __shfl_xor_sync(0xffffffffu, s1, o);
            }
            if (v0) wmax = fmaxf(wmax, s0);
            if (v1) wmax = fmaxf(wmax, s1);
            if (!lane) {
                if (v0) sc[r0] = s0;
                if (v1) sc[r1] = s1;
            }
        }
        if (!lane) red[warp] = wmax;
    }
    __syncthreads();   // sc + red visible

    // ---- pass B: global max + exp/sum ----
    if (warp == 0) {
        float mv = (lane < 16) ? red[lane] : -1e30f;
        for (int o = 8; o; o >>= 1) mv = fmaxf(mv, __shfl_xor_sync(0xffffffffu, mv, o));
        if (!lane) ctl[0] = mv;
    }
    __syncthreads();
    {
        float m = ctl[0];
        float w = (tid < 250) ? __expf(sc[tid] - m) : 0.f;
        if (tid < 250) wts[tid] = w;
        for (int o = 16; o; o >>= 1) w += __shfl_xor_sync(0xffffffffu, w, o);
        if (!lane) red2[warp] = w;
    }
    __syncthreads();

    // ---- pass C: accumulate. group g rows [125g,125g+125), thread owns 4 dims, 2-row ILP ----
    {
        int g = tid >> 8, tl = tid & 255;
        const __nv_bfloat16* base2 = gbase + 4 * tl + (size_t)(g * 125) * 1024;
        float4 acc0 = make_float4(0.f, 0.f, 0.f, 0.f);
        float4 acc1 = make_float4(0.f, 0.f, 0.f, 0.f);
        const float* wp2 = wts + g * 125;
#pragma unroll 6
        for (int r = 0; r < 124; r += 2) {
            float w0 = wp2[r], w1 = wp2[r + 1];
            uint2 q0 = *(const uint2*)(base2 + (size_t)r * 1024);
            uint2 q1 = *(const uint2*)(base2 + (size_t)(r + 1) * 1024);
            float2 a0 = bf2f(q0.x), a1 = bf2f(q0.y);
            float2 b0 = bf2f(q1.x), b1 = bf2f(q1.y);
            acc0.x += w0 * a0.x; acc0.y += w0 * a0.y;
            acc0.z += w0 * a1.x; acc0.w += w0 * a1.y;
            acc1.x += w1 * b0.x; acc1.y += w1 * b0.y;
            acc1.z += w1 * b1.x; acc1.w += w1 * b1.y;
        }
        {
            float w0 = wp2[124];
            uint2 q0 = *(const uint2*)(base2 + (size_t)124 * 1024);
            float2 a0 = bf2f(q0.x), a1 = bf2f(q0.y);
            acc0.x += w0 * a0.x; acc0.y += w0 * a0.y;
            acc0.z += w0 * a1.x; acc0.w += w0 * a1.y;
        }
        float4 acc = make_float4(acc0.x + acc1.x, acc0.y + acc1.y,
                                 acc0.z + acc1.z, acc0.w + acc1.w);
        if (g == 1) ((float4*)pacc)[tl] = acc;
        __syncthreads();
        if (g == 0) {
            float4 o = ((float4*)pacc)[tl];
            acc.x += o.x; acc.y += o.y; acc.z += o.z; acc.w += o.w;
            ((float4*)g_apart[h][b])[tl] = acc;
            if (tl == 0) {
                g_m[b][h] = ctl[0];
                float l = 0.f;
#pragma unroll
                for (int i = 0; i < 16; i++) l += red2[i];
                g_l[b][h] = l;
            }
        }
    }
}

// ---------------- LSTM 1: 4-way split-K, quarter-local barriers, pipelined x ----------------
__device__ void lstm1_phase(int t, int cb, float* smem) {
    int p = t & 1, q = p ^ 1;
    int tid = threadIdx.x;
    int quar = tid >> 7, tl = tid & 127;
    int b = tl & 63, jj = tl >> 6;
    float* xsq = smem + XS_OFF + quar * 2048;
    const float4* wp = (const float4*)(smem + W1T_OFF);

    int jc0 = cb * 4 + jj, jc1 = jc0 + 2;
    float2 A0g01, A0g23, A1g01, A1g23;
    if (quar == 0) {
        int vv = g_idx[b];
        A0g01 = make_float2(g_E[vv][0][jc0], g_E[vv][1][jc0]);
        A0g23 = make_float2(g_E[vv][2][jc0], g_E[vv][3][jc0]);
        A1g01 = make_float2(g_E[vv][0][jc1], g_E[vv][1][jc1]);
        A1g23 = make_float2(g_E[vv][2][jc1], g_E[vv][3][jc1]);
    } else {
        A0g01 = make_float2(0.f, 0.f); A0g23 = make_float2(0.f, 0.f);
        A1g01 = make_float2(0.f, 0.f); A1g23 = make_float2(0.f, 0.f);
    }

    int bq = tl >> 1;
    int kh = (tl & 1) * 16;
    int kbase = quar * 384;

    // per-thread softmax-combine scales for bq (no smem producer stage)
    float s0v, s1v;
    {
        float m0 = g_m[bq][0], m1 = g_m[bq][1];
        float M = fmaxf(m0, m1);
        float e0 = __expf(m0 - M), e1 = __expf(m1 - M);
        float L = g_l[bq][0] * e0 + g_l[bq][1] * e1;
        s0v = e0 / L; s1v = e1 / L;
    }

    float4 xa0, xa1, xa2, xa3, xb0, xb1, xb2, xb3;
    xb0 = xb1 = xb2 = xb3 = make_float4(0.f, 0.f, 0.f, 0.f);
    {
        int k0 = kbase + kh;
        if (k0 < 1024) {
            xa0 = *(const float4*)&g_apart[0][bq][k0];
            xa1 = *(const float4*)&g_apart[0][bq][k0 + 4];
            xa2 = *(const float4*)&g_apart[0][bq][k0 + 8];
            xa3 = *(const float4*)&g_apart[0][bq][k0 + 12];
            xb0 = *(const float4*)&g_apart[1][bq][k0];
            xb1 = *(const float4*)&g_apart[1][bq][k0 + 4];
            xb2 = *(const float4*)&g_apart[1][bq][k0 + 8];
            xb3 = *(const float4*)&g_apart[1][bq][k0 + 12];
        } else {
            xa0 = *(const float4*)&g_h1[p][bq][k0 - 1024];
            xa1 = *(const float4*)&g_h1[p][bq][k0 - 1020];
            xa2 = *(const float4*)&g_h1[p][bq][k0 - 1016];
            xa3 = *(const float4*)&g_h1[p][bq][k0 - 1012];
        }
    }

    for (int kt = 0; kt < 12; kt++) {
        int kb = kbase + kt * 32;
        QBAR(quar);   // xs free (quarter-local)
        int k0 = kb + kh;
        if (k0 < 1024) {
            xsq[(kh + 0) * 64 + bq]  = s0v * xa0.x + s1v * xb0.x;
            xsq[(kh + 1) * 64 + bq]  = s0v * xa0.y + s1v * xb0.y;
            xsq[(kh + 2) * 64 + bq]  = s0v * xa0.z + s1v * xb0.z;
            xsq[(kh + 3) * 64 + bq]  = s0v * xa0.w + s1v * xb0.w;
            xsq[(kh + 4) * 64 + bq]  = s0v * xa1.x + s1v * xb1.x;
            xsq[(kh + 5) * 64 + bq]  = s0v * xa1.y + s1v * xb1.y;
            xsq[(kh + 6) * 64 + bq]  = s0v * xa1.z + s1v * xb1.z;
            xsq[(kh + 7) * 64 + bq]  = s0v * xa1.w + s1v * xb1.w;
            xsq[(kh + 8) * 64 + bq]  = s0v * xa2.x + s1v * xb2.x;
            xsq[(kh + 9) * 64 + bq]  = s0v * xa2.y + s1v * xb2.y;
            xsq[(kh + 10) * 64 + bq] = s0v * xa2.z + s1v * xb2.z;
            xsq[(kh + 11) * 64 + bq] = s0v * xa2.w + s1v * xb2.w;
            xsq[(kh + 12) * 64 + bq] = s0v * xa3.x + s1v * xb3.x;
            xsq[(kh + 13) * 64 + bq] = s0v * xa3.y + s1v * xb3.y;
            xsq[(kh + 14) * 64 + bq] = s0v * xa3.z + s1v * xb3.z;
            xsq[(kh + 15) * 64 + bq] = s0v * xa3.w + s1v * xb3.w;
        } else {
            xsq[(kh + 0) * 64 + bq]  = xa0.x; xsq[(kh + 1) * 64 + bq]  = xa0.y;
            xsq[(kh + 2) * 64 + bq]  = xa0.z; xsq[(kh + 3) * 64 + bq]  = xa0.w;
            xsq[(kh + 4) * 64 + bq]  = xa1.x; xsq[(kh + 5) * 64 + bq]  = xa1.y;
            xsq[(kh + 6) * 64 + bq]  = xa1.z; xsq[(kh + 7) * 64 + bq]  = xa1.w;
            xsq[(kh + 8) * 64 + bq]  = xa2.x; xsq[(kh + 9) * 64 + bq]  = xa2.y;
            xsq[(kh + 10) * 64 + bq] = xa2.z; xsq[(kh + 11) * 64 + bq] = xa2.w;
            xsq[(kh + 12) * 64 + bq] = xa3.x; xsq[(kh + 13) * 64 + bq] = xa3.y;
            xsq[(kh + 14) * 64 + bq] = xa3.z; xsq[(kh + 15) * 64 + bq] = xa3.w;
        }
        if (kt + 1 < 12) {
            int kn = kbase + (kt + 1) * 32 + kh;
            if (kn < 1024) {
                xa0 = *(const float4*)&g_apart[0][bq][kn];
                xa1 = *(const float4*)&g_apart[0][bq][kn + 4];
                xa2 = *(const float4*)&g_apart[0][bq][kn + 8];
                xa3 = *(const float4*)&g_apart[0][bq][kn + 12];
                xb0 = *(const float4*)&g_apart[1][bq][kn];
                xb1 = *(const float4*)&g_apart[1][bq][kn + 4];
                xb2 = *(const float4*)&g_apart[1][bq][kn + 8];
                xb3 = *(const float4*)&g_apart[1][bq][kn + 12];
            } else {
                xa0 = *(const float4*)&g_h1[p][bq][kn - 1024];
                xa1 = *(const float4*)&g_h1[p][bq][kn - 1020];
                xa2 = *(const float4*)&g_h1[p][bq][kn - 1016];
                xa3 = *(const float4*)&g_h1[p][bq][kn - 1012];
            }
        }
        QBAR(quar);   // xs ready (quarter-local)
#pragma unroll
        for (int k = 0; k < 32; k++) {
            float x = xsq[k * 64 + b];
            float4 w0 = wp[(kb + k) * 4 + jj];
            float4 w1 = wp[(kb + k) * 4 + jj + 2];
            float2 xx = make_float2(x, x);
            A0g01 = ffma2(make_float2(w0.x, w0.y), xx, A0g01);
            A0g23 = ffma2(make_float2(w0.z, w0.w), xx, A0g23);
            A1g01 = ffma2(make_float2(w1.x, w1.y), xx, A1g01);
            A1g23 = ffma2(make_float2(w1.z, w1.w), xx, A1g23);
        }
    }
    if (quar) {
        float4* dst = (float4*)(smem + PT_OFF + (quar - 1) * 1024);
        dst[tl * 2]     = make_float4(A0g01.x, A0g01.y, A0g23.x, A0g23.y);
        dst[tl * 2 + 1] = make_float4(A1g01.x, A1g01.y, A1g23.x, A1g23.y);
    }
    __syncthreads();
    if (quar == 0) {
        const float4* p1 = (const float4*)(smem + PT_OFF);
        const float4* p2 = (const float4*)(smem + PT_OFF + 1024);
        const float4* p3 = (const float4*)(smem + PT_OFF + 2048);
        float4 u = p1[tl * 2], v = p2[tl * 2], w = p3[tl * 2];
        float4 a = make_float4(A0g01.x + u.x + v.x + w.x, A0g01.y + u.y + v.y + w.y,
                               A0g23.x + u.z + v.z + w.z, A0g23.y + u.w + v.w + w.w);
        float si = sigm(a.x), sf = sigm(a.y), so = sigm(a.w);
        float tg = tanhf(a.z);
        float cn = sf * g_c1[b][jc0] + si * tg;
        g_c1[b][jc0] = cn;
        g_h1[q][b][jc0] = so * tanhf(cn);
        u = p1[tl * 2 + 1]; v = p2[tl * 2 + 1]; w = p3[tl * 2 + 1];
        a = make_float4(A1g01.x + u.x + v.x + w.x, A1g01.y + u.y + v.y + w.y,
                        A1g23.x + u.z + v.z + w.z, A1g23.y + u.w + v.w + w.w);
        si = sigm(a.x); sf = sigm(a.y); so = sigm(a.w);
        tg = tanhf(a.z);
        cn = sf * g_c1[b][jc1] + si * tg;
        g_c1[b][jc1] = cn;
        g_h1[q][b][jc1] = so * tanhf(cn);
    }
}

// ---------------- LSTM 2: 4-way split-K, quarter-local barriers, pipelined x ----------------
__device__ void lstm2_phase(int t, int cb, float* smem) {
    int p = t & 1, q = p ^ 1;
    int tid = threadIdx.x;
    int quar = tid >> 7, tl = tid & 127;
    int b = tl & 63, jj = tl >> 6;
    float* xsq = smem + XS_OFF + quar * 2048;
    const float4* wp = (const float4*)(smem + W2T_OFF);

    int jc0 = cb * 4 + jj, jc1 = jc0 + 2;
    float2 A0g01, A0g23, A1g01, A1g23;
    if (quar == 0) {
        A0g01 = make_float2(g_B2[0][jc0], g_B2[1][jc0]);
        A0g23 = make_float2(g_B2[2][jc0], g_B2[3][jc0]);
        A1g01 = make_float2(g_B2[0][jc1], g_B2[1][jc1]);
        A1g23 = make_float2(g_B2[2][jc1], g_B2[3][jc1]);
    } else {
        A0g01 = make_float2(0.f, 0.f); A0g23 = make_float2(0.f, 0.f);
        A1g01 = make_float2(0.f, 0.f); A1g23 = make_float2(0.f, 0.f);
    }

    int bq = tl >> 1;
    int kh = (tl & 1) * 16;
    int kbase = quar * 256;

    float4 xa0, xa1, xa2, xa3;
    {
        int k0 = kbase + kh;
        const float* src = (k0 < 512) ? &g_h1[q][bq][k0] : &g_h2[p][bq][k0 - 512];
        xa0 = *(const float4*)src;
        xa1 = *(const float4*)(src + 4);
        xa2 = *(const float4*)(src + 8);
        xa3 = *(const float4*)(src + 12);
    }

    for (int kt = 0; kt < 8; kt++) {
        int kb = kbase + kt * 32;
        QBAR(quar);
        xsq[(kh + 0) * 64 + bq]  = xa0.x; xsq[(kh + 1) * 64 + bq]  = xa0.y;
        xsq[(kh + 2) * 64 + bq]  = xa0.z; xsq[(kh + 3) * 64 + bq]  = xa0.w;
        xsq[(kh + 4) * 64 + bq]  = xa1.x; xsq[(kh + 5) * 64 + bq]  = xa1.y;
        xsq[(kh + 6) * 64 + bq]  = xa1.z; xsq[(kh + 7) * 64 + bq]  = xa1.w;
        xsq[(kh + 8) * 64 + bq]  = xa2.x; xsq[(kh + 9) * 64 + bq]  = xa2.y;
        xsq[(kh + 10) * 64 + bq] = xa2.z; xsq[(kh + 11) * 64 + bq] = xa2.w;
        xsq[(kh + 12) * 64 + bq] = xa3.x; xsq[(kh + 13) * 64 + bq] = xa3.y;
        xsq[(kh + 14) * 64 + bq] = xa3.z; xsq[(kh + 15) * 64 + bq] = xa3.w;
        if (kt + 1 < 8) {
            int kn = kbase + (kt + 1) * 32 + kh;
            const float* src = (kn < 512) ? &g_h1[q][bq][kn] : &g_h2[p][bq][kn - 512];
            xa0 = *(const float4*)src;
            xa1 = *(const float4*)(src + 4);
            xa2 = *(const float4*)(src + 8);
            xa3 = *(const float4*)(src + 12);
        }
        QBAR(quar);
#pragma unroll
        for (int k = 0; k < 32; k++) {
            float x = xsq[k * 64 + b];
            float4 w0 = wp[(kb + k) * 4 + jj];
            float4 w1 = wp[(kb + k) * 4 + jj + 2];
            float2 xx = make_float2(x, x);
            A0g01 = ffma2(make_float2(w0.x, w0.y), xx, A0g01);
            A0g23 = ffma2(make_float2(w0.z, w0.w), xx, A0g23);
            A1g01 = ffma2(make_float2(w1.x, w1.y), xx, A1g01);
            A1g23 = ffma2(make_float2(w1.z, w1.w), xx, A1g23);
        }
    }
    if (quar) {
        float4* dst = (float4*)(smem + PT_OFF + (quar - 1) * 1024);
        dst[tl * 2]     = make_float4(A0g01.x, A0g01.y, A0g23.x, A0g23.y);
        dst[tl * 2 + 1] = make_float4(A1g01.x, A1g01.y, A1g23.x, A1g23.y);
    }
    __syncthreads();
    if (quar == 0) {
        const float4* p1 = (const float4*)(smem + PT_OFF);
        const float4* p2 = (const float4*)(smem + PT_OFF + 1024);
        const float4* p3 = (const float4*)(smem + PT_OFF + 2048);
        float4 u = p1[tl * 2], v = p2[tl * 2], w = p3[tl * 2];
        float4 a = make_float4(A0g01.x + u.x + v.x + w.x, A0g01.y + u.y + v.y + w.y,
                               A0g23.x + u.z + v.z + w.z, A0g23.y + u.w + v.w + w.w);
        float si = sigm(a.x), sf = sigm(a.y), so = sigm(a.w);
        float tg = tanhf(a.z);
        float cn = sf * g_c2[b][jc0] + si * tg;
        g_c2[b][jc0] = cn;
        g_h2[q][b][jc0] = so * tanhf(cn);
        u = p1[tl * 2 + 1]; v = p2[tl * 2 + 1]; w = p3[tl * 2 + 1];
        a = make_float4(A1g01.x + u.x + v.x + w.x, A1g01.y + u.y + v.y + w.y,
                        A1g23.x + u.z + v.z + w.z, A1g23.y + u.w + v.w + w.w);
        si = sigm(a.x); sf = sigm(a.y); so = sigm(a.w);
        tg = tanhf(a.z);
        cn = sf * g_c2[b][jc1] + si * tg;
        g_c2[b][jc1] = cn;
        g_h2[q][b][jc1] = so * tanhf(cn);
    }
}

// ---------------- persistent kernel ----------------
__global__ void __launch_bounds__(NTHR, 1)
k_persist(const float* __restrict__ ctx, const int* __restrict__ tgt,
          const float* __restrict__ h1_0, const float* __restrict__ c1_0,
          const float* __restrict__ h2_0, const float* __restrict__ c2_0,
          const float* __restrict__ emb,
          const float* __restrict__ W_ih0, const float* __restrict__ W_hh0,
          const float* __restrict__ b_ih0, const float* __restrict__ b_hh0,
          const float* __restrict__ W_ih1, const float* __restrict__ W_hh1,
          const float* __restrict__ b_ih1, const float* __restrict__ b_hh1,
          const float* __restrict__ Wl, const float* __restrict__ blv,
          float* __restrict__ out, int out_size) {
    extern __shared__ __align__(16) float smem[];
    int blk = blockIdx.x;
    int tid = threadIdx.x;
    int warp = tid >> 5, lane = tid & 31;

    // ---- setup ----
    {
        int gi = blk * NTHR + tid;
        if (gi < NB * NH) {
            ((float*)g_h1[0])[gi] = h1_0[gi];
            ((float*)g_c1)[gi]    = c1_0[gi];
            ((float*)g_h2[0])[gi] = h2_0[gi];
            ((float*)g_c2)[gi]    = c2_0[gi];
        }
        if (gi < 4 * NH) ((float*)g_B2)[gi] = b_ih1[gi] + b_hh1[gi];
        if (blk == 0 && tid < NB) g_idx[tid] = tgt[tid * NT];
        // fp32 ctx -> bf16 copy (L2-resident working set)
        for (int i = gi; i < NB * NS * 512; i += GRID * NTHR) {
            float2 v = ((const float2*)ctx)[i];
            ((__nv_bfloat162*)g_ctxb)[i] = __floats2bfloat162_rn(v.x, v.y);
        }
        for (int r = blk * 16 + warp; r < NV * 2048; r += GRID * 16) {
            int v = r / 2048, row = r % 2048;
            const float* wr = W_ih0 + (size_t)row * 1536;
            const float* ev = emb + v * 512;
            float s = 0.f;
            for (int i = lane; i < 512; i += 32) s += wr[i] * ev[i];
            for (int o = 16; o; o >>= 1) s += __shfl_xor_sync(0xffffffffu, s, o);
            if (!lane) g_E[v][row >> 9][row & 511] = s + b_ih0[row] + b_hh0[row];
        }
        int cb = blk;
#pragma unroll 1
        for (int r = 0; r < 16; r++) {
            int g = r & 3, jj = r >> 2;
            int row = g * 512 + cb * 4 + jj;
            for (int k = tid; k < 1536; k += NTHR) {
                float v = (k < 1024) ? W_ih0[(size_t)row * 1536 + 512 + k]
                                     : W_hh0[(size_t)row * 512 + (k - 1024)];
                smem[W1T_OFF + k * 16 + r] = v;
            }
            for (int k = tid; k < 1024; k += NTHR) {
                float v = (k < 512) ? W_ih1[(size_t)row * 512 + k]
                                    : W_hh1[(size_t)row * 512 + (k - 512)];
                smem[W2T_OFF + k * 16 + r] = v;
            }
        }
    }
    gbar(blk);

    for (int t = 0; t <= NT; t++) {
        attn_phase(Wl, blv, out, t, blk, smem);
        if (t == NT) break;
        gbar(blk);
        lstm1_phase(t, blk, smem);
        gbar(blk);
        lstm2_phase(t, blk, smem);
        gbar(blk);
    }

    if (out_size >= NB * NT * NV + NB * NT) {
        int i = blk * NTHR + tid;
        if (i < NB * NT) out[NB * NT * NV + i] = (float)tgt[i];
    }
}

// ---------------- launch ----------------
extern "C" void kernel_launch(void* const* d_in, const int* in_sizes, int n_in,
                              void* d_out, int out_size) {
    int off = (n_in >= 18) ? 0 : -1;
    const float* ctx   = (const float*)d_in[0];
    const int*   tgt   = (const int*)d_in[1];
    const float* h1_0  = (const float*)d_in[3 + off];
    const float* c1_0  = (const float*)d_in[4 + off];
    const float* h2_0  = (const float*)d_in[5 + off];
    const float* c2_0  = (const float*)d_in[6 + off];
    const float* emb   = (const float*)d_in[7 + off];
    const float* W_ih0 = (const float*)d_in[8 + off];
    const float* W_hh0 = (const float*)d_in[9 + off];
    const float* b_ih0 = (const float*)d_in[10 + off];
    const float* b_hh0 = (const float*)d_in[11 + off];
    const float* W_ih1 = (const float*)d_in[12 + off];
    const float* W_hh1 = (const float*)d_in[13 + off];
    const float* b_ih1 = (const float*)d_in[14 + off];
    const float* b_hh1 = (const float*)d_in[15 + off];
    const float* Wl    = (const float*)d_in[16 + off];
    const float* bl    = (const float*)d_in[17 + off];
    float* out = (float*)d_out;

    cudaFuncSetAttribute(k_persist, cudaFuncAttributeMaxDynamicSharedMemorySize, SMEM_BYTES);
    k_persist<<<GRID, NTHR, SMEM_BYTES>>>(ctx, tgt, h1_0, c1_0, h2_0, c2_0, emb,
                                          W_ih0, W_hh0, b_ih0, b_hh0,
                                          W_ih1, W_hh1, b_ih1, b_hh1,
                                          Wl, bl, out, out_size);
}